// round 12
// baseline (speedup 1.0000x reference)
#include <cuda_runtime.h>
#include <cuda_fp16.h>
#include <cstdint>
#include <math.h>

#define B_ 512
#define T_ 96
#define F_ 128
#define H_ 512
#define TB_ (T_*B_)        // 49152
#define BTF_ (B_*T_*F_)    // 6291456
#define KG_ 768            // gates GEMM K = 2F + H
#define NG_ 2048           // 4H

typedef unsigned int u32;

// ---------------- scratch (device globals: no allocation allowed) ----------------
__device__ __align__(16) __half g_d16[TB_*F_];     // delta (integer-valued, fp16 exact)
__device__ float g_gammah[TB_*H_];                 // [t*B+b, h]
__device__ __align__(16) __half g_A216[TB_*2*F_];  // [t*B+b, gx|m]
__device__ float g_alpha[TB_*F_];
__device__ __align__(16) __half g_A16[B_*KG_];     // per-step A = [c_c | m | h*gamma]
__device__ float g_c[B_*H_];
__device__ float g_h[B_*H_];
__device__ float g_Gh[B_*NG_];                     // partial gates from h-slice
__device__ __align__(16) __half g_Wg16[NG_*KG_];   // [Wih|Whh] fused, gate-interleaved
__device__ float g_bgR[NG_];                       // bih+bhh, gate-interleaved
__device__ __align__(16) __half g_Wdh16[H_*F_];
__device__ __align__(16) __half g_WdhR[H_*F_];     // (W - fp16(W))*1024
__device__ __align__(16) __half g_Wc16[F_*2*F_];
__device__ __align__(16) __half g_WcR[F_*2*F_];

__device__ __forceinline__ float sigmoidf_(float v){ return 1.f/(1.f+expf(-v)); }

__device__ __forceinline__ u32 sptr(const void* p){
    return (u32)__cvta_generic_to_shared(p);
}

__device__ __forceinline__ void ldsm4(u32* r, u32 addr){
    asm volatile("ldmatrix.sync.aligned.m8n8.x4.shared.b16 {%0,%1,%2,%3}, [%4];"
        : "=r"(r[0]),"=r"(r[1]),"=r"(r[2]),"=r"(r[3]) : "r"(addr));
}

__device__ __forceinline__ void mma16816h(float* c, const u32* a, u32 b0, u32 b1){
    asm volatile("mma.sync.aligned.m16n8k16.row.col.f32.f16.f16.f32 "
        "{%0,%1,%2,%3},{%4,%5,%6,%7},{%8,%9},{%0,%1,%2,%3};"
        : "+f"(c[0]),"+f"(c[1]),"+f"(c[2]),"+f"(c[3])
        : "r"(a[0]),"r"(a[1]),"r"(a[2]),"r"(a[3]), "r"(b0),"r"(b1));
}

__device__ __forceinline__ void cpasync16(u32 dst, const void* src){
    asm volatile("cp.async.cg.shared.global [%0], [%1], 16;" :: "r"(dst), "l"(src));
}

// ---------------- setup ----------------
__global__ void k_setup(const float* __restrict__ Wih, const float* __restrict__ Whh,
                        const float* __restrict__ bih, const float* __restrict__ bhh,
                        const float* __restrict__ Wdh, const float* __restrict__ Wc){
    int tid0 = blockIdx.x*blockDim.x + threadIdx.x;
    int stride = gridDim.x*blockDim.x;
    for (int idx = tid0; idx < NG_*KG_; idx += stride){
        int n = idx / KG_;
        int k = idx - n*KG_;
        int j = n >> 2, g = n & 3;
        int no = g*512 + j;
        float v = (k < 256) ? Wih[no*256 + k] : Whh[no*H_ + (k-256)];
        g_Wg16[idx] = __float2half(v);
    }
    for (int idx = tid0; idx < H_*F_; idx += stride){
        float v = Wdh[idx];
        __half h = __float2half(v);
        g_Wdh16[idx] = h;
        g_WdhR[idx]  = __float2half((v - __half2float(h))*1024.f);
    }
    for (int idx = tid0; idx < F_*2*F_; idx += stride){
        float v = Wc[idx];
        __half h = __float2half(v);
        g_Wc16[idx] = h;
        g_WcR[idx]  = __float2half((v - __half2float(h))*1024.f);
    }
    for (int idx = tid0; idx < B_*H_; idx += stride){
        g_c[idx] = 0.f;
        g_h[idx] = 0.f;
        g_A16[(idx >> 9)*KG_ + 256 + (idx & 511)] = __float2half(0.f);
    }
    if (tid0 < NG_){
        int j = tid0 >> 2, g = tid0 & 3;
        int no = g*512 + j;
        g_bgR[tid0] = bih[no] + bhh[no];
    }
}

// ---------------- delta scan + gamma_x + alpha-input (fused) ----------------
__global__ void k_delta2(const int* __restrict__ mask, const float* __restrict__ Wdx,
                         const float* __restrict__ bdx){
    int idx = blockIdx.x*blockDim.x + threadIdx.x;
    int b = idx >> 7, f = idx & 127;
    const float wdx = Wdx[f*F_ + f];
    const float bx  = bdx[f];
    const int base = b*T_*F_ + f;
    float d = 0.f;
    for (int t = 0; t < T_; t++){
        int o = t*B_ + b;
        g_d16[o*F_ + f] = __float2half(d);
        float gx = expf(-fmaxf(d*wdx + bx, 0.f));
        float mp = (float)mask[base + t*F_];
        g_A216[o*256 + f]       = __float2half(gx);
        g_A216[o*256 + 128 + f] = __float2half(mp);
        d = mp + (1.f - mp)*(d + 1.f);
    }
}

// ---------------- 2-pass fp16 GEMM (precompute) ----------------
#define SSTR 72
#define R2P 320
#define B2P (R2P*SSTR)
#define SM2P (2*B2P*2)

template<int EPI>
__global__ void __launch_bounds__(256, 1)
gemm_2p(const __half* __restrict__ A, const __half* __restrict__ W,
        const __half* __restrict__ Wr, const float* __restrict__ bias,
        float* __restrict__ C, int N, int K)
{
    extern __shared__ __align__(16) __half smh[];
    const int tid = threadIdx.x, lane = tid & 31, wid = tid >> 5;
    const int m0 = blockIdx.y*64, n0 = blockIdx.x*128;
    const int wm = (wid & 1)*32, wn = (wid >> 1)*32;
    const int NC = K >> 6;

    float acc1[2][4][4], acc2[2][4][4];
    #pragma unroll
    for (int i=0;i<2;i++)
        #pragma unroll
        for (int j=0;j<4;j++)
            #pragma unroll
            for (int q=0;q<4;q++){ acc1[i][j][q]=0.f; acc2[i][j][q]=0.f; }

    const int aRow = lane & 15;
    const int aCol = ((lane >> 4) & 1) * 8;
    const int bRow = (lane & 7) + ((lane >> 4) & 1) * 8;
    const int bCol = ((lane >> 3) & 1) * 8;

    const __half* s_src[10]; int s_row[10];
    #pragma unroll
    for (int j = 0; j < 10; j++){
        int u = tid + j*256; int r = u >> 3;
        if (r < 64)      { s_src[j] = A;  s_row[j] = m0 + r; }
        else if (r < 192){ s_src[j] = W;  s_row[j] = n0 + r - 64; }
        else             { s_src[j] = Wr; s_row[j] = n0 + r - 192; }
    }

    {
        #pragma unroll
        for (int j = 0; j < 10; j++){
            int u = tid + j*256; int r = u >> 3, c = (u & 7)*8;
            cpasync16(sptr(&smh[r*SSTR + c]), &s_src[j][(size_t)s_row[j]*K + c]);
        }
        asm volatile("cp.async.commit_group;" ::: "memory");
    }

    for (int ch = 0; ch < NC; ch++){
        if (ch + 1 < NC){
            __half* tb = smh + ((ch+1)&1)*B2P;
            const int k1 = (ch+1)*64;
            #pragma unroll
            for (int j = 0; j < 10; j++){
                int u = tid + j*256; int r = u >> 3, c = (u & 7)*8;
                cpasync16(sptr(&tb[r*SSTR + c]), &s_src[j][(size_t)s_row[j]*K + k1 + c]);
            }
            asm volatile("cp.async.commit_group;" ::: "memory");
            asm volatile("cp.async.wait_group 1;" ::: "memory");
        } else {
            asm volatile("cp.async.wait_group 0;" ::: "memory");
        }
        __syncthreads();

        const __half* bb = smh + (ch&1)*B2P;
        const __half* As = bb;
        const __half* Ws = bb + 64*SSTR;
        const __half* Rs = bb + 192*SSTR;

        #pragma unroll
        for (int kk = 0; kk < 64; kk += 16){
            u32 a[2][4], bw[2][4], br[2][4];
            #pragma unroll
            for (int mt = 0; mt < 2; mt++)
                ldsm4(a[mt], sptr(&As[(wm + mt*16 + aRow)*SSTR + kk + aCol]));
            #pragma unroll
            for (int nt = 0; nt < 2; nt++){
                ldsm4(bw[nt], sptr(&Ws[(wn + nt*16 + bRow)*SSTR + kk + bCol]));
                ldsm4(br[nt], sptr(&Rs[(wn + nt*16 + bRow)*SSTR + kk + bCol]));
            }
            #pragma unroll
            for (int mt = 0; mt < 2; mt++)
                #pragma unroll
                for (int nj = 0; nj < 4; nj++){
                    const u32* pw = &bw[nj >> 1][(nj & 1) * 2];
                    const u32* pr = &br[nj >> 1][(nj & 1) * 2];
                    mma16816h(acc1[mt][nj], a[mt], pw[0], pw[1]);
                    mma16816h(acc2[mt][nj], a[mt], pr[0], pr[1]);
                }
        }
        __syncthreads();
    }

    const float rs = 1.f/1024.f;
    #pragma unroll
    for (int mt = 0; mt < 2; mt++){
        int row = m0 + wm + mt*16 + (lane >> 2);
        #pragma unroll
        for (int nj = 0; nj < 4; nj++){
            int col = n0 + wn + nj*8 + (lane & 3)*2;
            float b0v = bias[col], b1v = bias[col+1];
            float v[4] = { acc1[mt][nj][0] + acc2[mt][nj][0]*rs + b0v,
                           acc1[mt][nj][1] + acc2[mt][nj][1]*rs + b1v,
                           acc1[mt][nj][2] + acc2[mt][nj][2]*rs + b0v,
                           acc1[mt][nj][3] + acc2[mt][nj][3]*rs + b1v };
            #pragma unroll
            for (int q = 0; q < 4; q++){
                if (EPI == 1)      v[q] = expf(-fmaxf(v[q], 0.f));
                else if (EPI == 2) v[q] = 1.f/(1.f+expf(-v[q]));
            }
            C[(size_t)row*N + col]         = v[0];
            C[(size_t)row*N + col + 1]     = v[1];
            C[(size_t)(row+8)*N + col]     = v[2];
            C[(size_t)(row+8)*N + col + 1] = v[3];
        }
    }
}

// ---------------- fused per-step kernel: gates_h (bids 0-127) + step work (128-143) --
#define RG 192
#define BG (RG*SSTR)
#define SMG (2*BG*2)               // 55296: gemm_gc dynamic smem
#define SMP 115328                 // k_par dynamic smem (step path layout)

__global__ void __launch_bounds__(256, 1)
k_par(int t, const float* __restrict__ x, const int* __restrict__ mask,
      const float* __restrict__ Wh, const float* __restrict__ bh,
      const float* __restrict__ Wf, const float* __restrict__ bf,
      float* __restrict__ out)
{
    extern __shared__ __align__(16) char smraw[];
    const int tid = threadIdx.x;

    if (blockIdx.x < 128){
        // ===== gates_h: Gh = A16[:,256:768] @ Wg16[:,256:768]^T  (K=512) =====
        if (t >= T_-1) return;
        __half* smh = (__half*)smraw;
        const __half* A = g_A16 + 256;
        const __half* W = g_Wg16 + 256;
        const int lane = tid & 31, wid = tid >> 5;
        const int m0 = (blockIdx.x >> 4)*64;       // 8 m-tiles
        const int n0 = (blockIdx.x & 15)*128;      // 16 n-tiles
        const int wm = (wid & 1)*32, wn = (wid >> 1)*32;
        const int NC = 8;                          // K=512

        float acc[2][4][4];
        #pragma unroll
        for (int i=0;i<2;i++)
            #pragma unroll
            for (int j=0;j<4;j++)
                #pragma unroll
                for (int q=0;q<4;q++) acc[i][j][q] = 0.f;

        const int aRow = lane & 15;
        const int aCol = ((lane >> 4) & 1) * 8;
        const int bRow = (lane & 7) + ((lane >> 4) & 1) * 8;
        const int bCol = ((lane >> 3) & 1) * 8;

        const __half* s_src[6]; int s_row[6];
        #pragma unroll
        for (int j = 0; j < 6; j++){
            int u = tid + j*256; int r = u >> 3;
            if (r < 64){ s_src[j] = A; s_row[j] = m0 + r; }
            else       { s_src[j] = W; s_row[j] = n0 + r - 64; }
        }

        {
            #pragma unroll
            for (int j = 0; j < 6; j++){
                int u = tid + j*256; int r = u >> 3, c = (u & 7)*8;
                cpasync16(sptr(&smh[r*SSTR + c]), &s_src[j][(size_t)s_row[j]*KG_ + c]);
            }
            asm volatile("cp.async.commit_group;" ::: "memory");
        }

        for (int ch = 0; ch < NC; ch++){
            if (ch + 1 < NC){
                __half* tb = smh + ((ch+1)&1)*BG;
                const int k1 = (ch+1)*64;
                #pragma unroll
                for (int j = 0; j < 6; j++){
                    int u = tid + j*256; int r = u >> 3, c = (u & 7)*8;
                    cpasync16(sptr(&tb[r*SSTR + c]), &s_src[j][(size_t)s_row[j]*KG_ + k1 + c]);
                }
                asm volatile("cp.async.commit_group;" ::: "memory");
                asm volatile("cp.async.wait_group 1;" ::: "memory");
            } else {
                asm volatile("cp.async.wait_group 0;" ::: "memory");
            }
            __syncthreads();

            const __half* bb = smh + (ch&1)*BG;
            const __half* As = bb;
            const __half* Ws = bb + 64*SSTR;

            #pragma unroll
            for (int kk = 0; kk < 64; kk += 16){
                u32 a[2][4], b[2][4];
                #pragma unroll
                for (int mt = 0; mt < 2; mt++)
                    ldsm4(a[mt], sptr(&As[(wm + mt*16 + aRow)*SSTR + kk + aCol]));
                #pragma unroll
                for (int nt = 0; nt < 2; nt++)
                    ldsm4(b[nt], sptr(&Ws[(wn + nt*16 + bRow)*SSTR + kk + bCol]));
                #pragma unroll
                for (int mt = 0; mt < 2; mt++)
                    #pragma unroll
                    for (int nj = 0; nj < 4; nj++){
                        const u32* pb = &b[nj >> 1][(nj & 1) * 2];
                        mma16816h(acc[mt][nj], a[mt], pb[0], pb[1]);
                    }
            }
            __syncthreads();
        }

        #pragma unroll
        for (int mt = 0; mt < 2; mt++){
            int row = m0 + wm + mt*16 + (lane >> 2);
            #pragma unroll
            for (int nj = 0; nj < 4; nj++){
                int col = n0 + wn + nj*8 + (lane & 3)*2;
                g_Gh[(size_t)row*NG_ + col]         = acc[mt][nj][0];
                g_Gh[(size_t)row*NG_ + col + 1]     = acc[mt][nj][1];
                g_Gh[(size_t)(row+8)*NG_ + col]     = acc[mt][nj][2];
                g_Gh[(size_t)(row+8)*NG_ + col + 1] = acc[mt][nj][3];
            }
        }
    } else {
        // ===== step work: 32 batches per CTA (16 CTAs) =====
        float* hs     = (float*)smraw;             // [32][512]
        float* Wt     = hs + 32*512;               // [32][129]
        float* xh_s   = Wt + 32*129;               // [32][128]
        float* xc_s   = xh_s + 32*128;             // [32][128]
        float* wfdiag = xc_s + 32*128;             // [128]
        const int b0 = (blockIdx.x - 128)*32;
        const int n  = tid & 127;
        const int g  = tid >> 7;                   // batch halves: g*16..g*16+15

        if (tid < 128) wfdiag[tid] = Wf[tid*F_ + tid];
        for (int idx = tid; idx < 32*128; idx += 256){   // float4 units
            int b = idx >> 7, q = idx & 127;
            ((float4*)hs)[b*128 + q] = ((const float4*)&g_h[(size_t)(b0+b)*H_])[q];
        }
        __syncthreads();

        // ---- x_h = h @ Wh^T + bh ----
        float acc[16];
        #pragma unroll
        for (int b = 0; b < 16; b++) acc[b] = 0.f;
        for (int k0 = 0; k0 < H_; k0 += 32){
            for (int idx = tid; idx < 128*32; idx += 256){
                int nn = idx >> 5, kk = idx & 31;
                Wt[kk*129 + nn] = Wh[nn*H_ + k0 + kk];
            }
            __syncthreads();
            #pragma unroll
            for (int k4 = 0; k4 < 8; k4++){
                float w0 = Wt[(k4*4+0)*129 + n];
                float w1 = Wt[(k4*4+1)*129 + n];
                float w2 = Wt[(k4*4+2)*129 + n];
                float w3 = Wt[(k4*4+3)*129 + n];
                #pragma unroll
                for (int b = 0; b < 16; b++){
                    float4 hv = *(const float4*)&hs[(g*16+b)*512 + k0 + k4*4];
                    acc[b] += w0*hv.x + w1*hv.y + w2*hv.z + w3*hv.w;
                }
            }
            __syncthreads();
        }

        float m_r[16], x_r[16];
        {
            float bhv = bh[n];
            #pragma unroll
            for (int b = 0; b < 16; b++){
                int gb = b0 + g*16 + b;
                float xh = acc[b] + bhv;
                xh_s[(g*16+b)*128 + n] = xh;
                int gi = gb*T_*F_ + t*F_ + n;
                float mv = (float)mask[gi];
                float xv = x[gi];
                m_r[b] = mv; x_r[b] = xv;
                xc_s[(g*16+b)*128 + n] = mv*xv + (1.f - mv)*xh;
                out[3*BTF_ + gi] = xh;
            }
        }
        __syncthreads();

        // ---- z_h = x_c @ Wf^T (off-diag) + bf ----
        float acc2[16];
        #pragma unroll
        for (int b = 0; b < 16; b++) acc2[b] = 0.f;
        for (int k0 = 0; k0 < F_; k0 += 32){
            for (int idx = tid; idx < 128*32; idx += 256){
                int nn = idx >> 5, kk = idx & 31;
                Wt[kk*129 + nn] = Wf[nn*F_ + k0 + kk];
            }
            __syncthreads();
            #pragma unroll
            for (int k4 = 0; k4 < 8; k4++){
                float w0 = Wt[(k4*4+0)*129 + n];
                float w1 = Wt[(k4*4+1)*129 + n];
                float w2 = Wt[(k4*4+2)*129 + n];
                float w3 = Wt[(k4*4+3)*129 + n];
                #pragma unroll
                for (int b = 0; b < 16; b++){
                    float4 xv4 = *(const float4*)&xc_s[(g*16+b)*128 + k0 + k4*4];
                    acc2[b] += w0*xv4.x + w1*xv4.y + w2*xv4.z + w3*xv4.w;
                }
            }
            __syncthreads();
        }

        {
            float bfv = bf[n];
            float wfd = wfdiag[n];
            #pragma unroll
            for (int b = 0; b < 16; b++){
                int gb = b0 + g*16 + b;
                float xc = xc_s[(g*16+b)*128 + n];
                float z  = acc2[b] + bfv - xc*wfd;
                float al = g_alpha[(size_t)(t*B_ + gb)*F_ + n];
                float xh = xh_s[(g*16+b)*128 + n];
                float ch = al*z + (1.f - al)*xh;
                float cc = m_r[b]*x_r[b] + (1.f - m_r[b])*ch;
                int gi = gb*T_*F_ + t*F_ + n;
                out[gi]          = cc;
                out[BTF_  + gi]  = ch;
                out[2*BTF_+ gi]  = z;
                g_A16[gb*KG_ + n]       = __float2half(cc);
                g_A16[gb*KG_ + 128 + n] = __float2half(m_r[b]);
            }
        }
    }
}

// ---------------- gates_cm (K=256) + Gh + fused LSTM epilogue ----------------
__global__ void __launch_bounds__(256, 1)
gemm_gc(int t)
{
    extern __shared__ __align__(16) __half smh[];
    const __half* A = g_A16;
    const __half* W = g_Wg16;
    const int tid = threadIdx.x, lane = tid & 31, wid = tid >> 5;
    const int m0 = blockIdx.y*64, n0 = blockIdx.x*128;
    const int wm = (wid & 1)*32, wn = (wid >> 1)*32;
    const int NC = 4;                          // K=256

    float acc[2][4][4];
    #pragma unroll
    for (int i=0;i<2;i++)
        #pragma unroll
        for (int j=0;j<4;j++)
            #pragma unroll
            for (int q=0;q<4;q++) acc[i][j][q] = 0.f;

    const int aRow = lane & 15;
    const int aCol = ((lane >> 4) & 1) * 8;
    const int bRow = (lane & 7) + ((lane >> 4) & 1) * 8;
    const int bCol = ((lane >> 3) & 1) * 8;

    const __half* s_src[6]; int s_row[6];
    #pragma unroll
    for (int j = 0; j < 6; j++){
        int u = tid + j*256; int r = u >> 3;
        if (r < 64){ s_src[j] = A; s_row[j] = m0 + r; }
        else       { s_src[j] = W; s_row[j] = n0 + r - 64; }
    }

    {
        #pragma unroll
        for (int j = 0; j < 6; j++){
            int u = tid + j*256; int r = u >> 3, c = (u & 7)*8;
            cpasync16(sptr(&smh[r*SSTR + c]), &s_src[j][(size_t)s_row[j]*KG_ + c]);
        }
        asm volatile("cp.async.commit_group;" ::: "memory");
    }

    for (int ch = 0; ch < NC; ch++){
        if (ch + 1 < NC){
            __half* tb = smh + ((ch+1)&1)*BG;
            const int k1 = (ch+1)*64;
            #pragma unroll
            for (int j = 0; j < 6; j++){
                int u = tid + j*256; int r = u >> 3, c = (u & 7)*8;
                cpasync16(sptr(&tb[r*SSTR + c]), &s_src[j][(size_t)s_row[j]*KG_ + k1 + c]);
            }
            asm volatile("cp.async.commit_group;" ::: "memory");
            asm volatile("cp.async.wait_group 1;" ::: "memory");
        } else {
            asm volatile("cp.async.wait_group 0;" ::: "memory");
        }
        __syncthreads();

        const __half* bb = smh + (ch&1)*BG;
        const __half* As = bb;
        const __half* Ws = bb + 64*SSTR;

        #pragma unroll
        for (int kk = 0; kk < 64; kk += 16){
            u32 a[2][4], b[2][4];
            #pragma unroll
            for (int mt = 0; mt < 2; mt++)
                ldsm4(a[mt], sptr(&As[(wm + mt*16 + aRow)*SSTR + kk + aCol]));
            #pragma unroll
            for (int nt = 0; nt < 2; nt++)
                ldsm4(b[nt], sptr(&Ws[(wn + nt*16 + bRow)*SSTR + kk + bCol]));
            #pragma unroll
            for (int mt = 0; mt < 2; mt++)
                #pragma unroll
                for (int nj = 0; nj < 4; nj++){
                    const u32* pb = &b[nj >> 1][(nj & 1) * 2];
                    mma16816h(acc[mt][nj], a[mt], pb[0], pb[1]);
                }
        }
        __syncthreads();
    }

    // ---- epilogue: gates = acc + bias + Gh; then LSTM update ----
    float* Cs = (float*)smh;   // 64x128 fp32 = 32KB overlay
    #pragma unroll
    for (int mt = 0; mt < 2; mt++){
        int rl = wm + mt*16 + (lane >> 2);
        #pragma unroll
        for (int nj = 0; nj < 4; nj++){
            int cl = wn + nj*8 + (lane & 3)*2;
            float b0v = g_bgR[n0 + cl], b1v = g_bgR[n0 + cl + 1];
            const float* gh0 = &g_Gh[(size_t)(m0+rl)*NG_ + n0 + cl];
            const float* gh8 = &g_Gh[(size_t)(m0+rl+8)*NG_ + n0 + cl];
            Cs[rl*128 + cl]         = acc[mt][nj][0] + b0v + gh0[0];
            Cs[rl*128 + cl + 1]     = acc[mt][nj][1] + b1v + gh0[1];
            Cs[(rl+8)*128 + cl]     = acc[mt][nj][2] + b0v + gh8[0];
            Cs[(rl+8)*128 + cl + 1] = acc[mt][nj][3] + b1v + gh8[1];
        }
    }
    __syncthreads();

    const int u0 = n0 >> 2;   // 32 hidden units per CTA
    #pragma unroll
    for (int i = 0; i < 8; i++){
        int cidx = tid + i*256;
        int bl = cidx >> 5, jl = cidx & 31;
        float4 gv = *(const float4*)&Cs[bl*128 + jl*4];   // i, f, g, o
        float ig = sigmoidf_(gv.x);
        float fg = sigmoidf_(gv.y);
        float gg = tanhf(gv.z);
        float og = sigmoidf_(gv.w);
        int gb = m0 + bl;
        int ju = u0 + jl;
        float c = fg * g_c[gb*H_ + ju] + ig*gg;
        g_c[gb*H_ + ju] = c;
        float h = og * tanhf(c);
        g_h[gb*H_ + ju] = h;
        float hd = h * g_gammah[(size_t)((t+1)*B_ + gb)*H_ + ju];
        g_A16[gb*KG_ + 256 + ju] = __float2half(hd);
    }
}

// ---------------- launch ----------------
extern "C" void kernel_launch(void* const* d_in, const int* in_sizes, int n_in,
                              void* d_out, int out_size)
{
    const float* x    = (const float*)d_in[0];
    const int*   mask = (const int*  )d_in[1];
    const float* Wdh  = (const float*)d_in[2];
    const float* bdh  = (const float*)d_in[3];
    const float* Wdx  = (const float*)d_in[4];
    const float* bdx  = (const float*)d_in[5];
    const float* Wh   = (const float*)d_in[6];
    const float* bh   = (const float*)d_in[7];
    const float* Wf   = (const float*)d_in[8];
    const float* bf   = (const float*)d_in[9];
    const float* Wc   = (const float*)d_in[10];
    const float* bc   = (const float*)d_in[11];
    const float* Wih  = (const float*)d_in[12];
    const float* Whh  = (const float*)d_in[13];
    const float* bih  = (const float*)d_in[14];
    const float* bhh  = (const float*)d_in[15];
    float* out = (float*)d_out;

    void *pD16, *pA216, *pWdh16, *pWdhR, *pWc16, *pWcR, *pGammah, *pAlpha;
    cudaGetSymbolAddress(&pD16,    g_d16);
    cudaGetSymbolAddress(&pA216,   g_A216);
    cudaGetSymbolAddress(&pWdh16,  g_Wdh16);
    cudaGetSymbolAddress(&pWdhR,   g_WdhR);
    cudaGetSymbolAddress(&pWc16,   g_Wc16);
    cudaGetSymbolAddress(&pWcR,    g_WcR);
    cudaGetSymbolAddress(&pGammah, g_gammah);
    cudaGetSymbolAddress(&pAlpha,  g_alpha);

    cudaFuncSetAttribute(gemm_2p<1>, cudaFuncAttributeMaxDynamicSharedMemorySize, SM2P);
    cudaFuncSetAttribute(gemm_2p<2>, cudaFuncAttributeMaxDynamicSharedMemorySize, SM2P);
    cudaFuncSetAttribute(k_par,      cudaFuncAttributeMaxDynamicSharedMemorySize, SMP);
    cudaFuncSetAttribute(gemm_gc,    cudaFuncAttributeMaxDynamicSharedMemorySize, SMG);

    // setup + time-parallel precomputes
    k_setup<<<2048, 256>>>(Wih, Whh, bih, bhh, Wdh, Wc);
    k_delta2<<<256, 256>>>(mask, Wdx, bdx);
    gemm_2p<1><<<dim3(H_/128, TB_/64), 256, SM2P>>>(
        (const __half*)pD16, (const __half*)pWdh16, (const __half*)pWdhR,
        bdh, (float*)pGammah, H_, F_);
    gemm_2p<2><<<dim3(F_/128, TB_/64), 256, SM2P>>>(
        (const __half*)pA216, (const __half*)pWc16, (const __half*)pWcR,
        bc, (float*)pAlpha, F_, 2*F_);

    // sequential recurrence: 96 steps
    for (int t = 0; t < T_; t++){
        // fused: gates_h (tensor, 128 CTAs) || step work (FFMA/mem, 16 CTAs)
        k_par<<<144, 256, SMP>>>(t, x, mask, Wh, bh, Wf, bf, out);
        if (t < T_ - 1){
            // gates_cm (K=256) + Gh + bias -> LSTM update
            gemm_gc<<<dim3(NG_/128, B_/64), 256, SMG>>>(t);
        }
    }
}

// round 13
// speedup vs baseline: 1.5543x; 1.5543x over previous
#include <cuda_runtime.h>
#include <cuda_fp16.h>
#include <cstdint>
#include <math.h>

#define B_ 512
#define T_ 96
#define F_ 128
#define H_ 512
#define TB_ (T_*B_)        // 49152
#define BTF_ (B_*T_*F_)    // 6291456
#define KG_ 768            // gates GEMM K = 2F + H
#define NG_ 2048           // 4H

typedef unsigned int u32;

// ---------------- scratch (device globals: no allocation allowed) ----------------
__device__ __align__(16) __half g_d16[TB_*F_];     // delta (integer-valued, fp16 exact)
__device__ float g_gammah[TB_*H_];                 // [t*B+b, h]
__device__ __align__(16) __half g_A216[TB_*2*F_];  // [t*B+b, gx|m]
__device__ float g_alpha[TB_*F_];
__device__ __align__(16) __half g_A16[B_*KG_];     // per-step A = [c_c | m | h*gamma]
__device__ float g_c[B_*H_];
__device__ float g_h[B_*H_];
__device__ __align__(16) __half g_Wg16[NG_*KG_];   // [Wih|Whh] fused, gate-interleaved
__device__ float g_bgR[NG_];                       // bih+bhh, gate-interleaved
__device__ __align__(16) __half g_Wdh16[H_*F_];
__device__ __align__(16) __half g_WdhR[H_*F_];     // (W - fp16(W))*1024
__device__ __align__(16) __half g_Wc16[F_*2*F_];
__device__ __align__(16) __half g_WcR[F_*2*F_];
__device__ __align__(16) __half g_Wh16[F_*H_];     // hist_reg weights fp16
__device__ __align__(16) __half g_Wf16[F_*F_];     // feat_reg weights fp16

__device__ __forceinline__ float sigmoidf_(float v){ return 1.f/(1.f+expf(-v)); }

__device__ __forceinline__ u32 sptr(const void* p){
    return (u32)__cvta_generic_to_shared(p);
}

__device__ __forceinline__ void ldsm4(u32* r, u32 addr){
    asm volatile("ldmatrix.sync.aligned.m8n8.x4.shared.b16 {%0,%1,%2,%3}, [%4];"
        : "=r"(r[0]),"=r"(r[1]),"=r"(r[2]),"=r"(r[3]) : "r"(addr));
}

__device__ __forceinline__ void mma16816h(float* c, const u32* a, u32 b0, u32 b1){
    asm volatile("mma.sync.aligned.m16n8k16.row.col.f32.f16.f16.f32 "
        "{%0,%1,%2,%3},{%4,%5,%6,%7},{%8,%9},{%0,%1,%2,%3};"
        : "+f"(c[0]),"+f"(c[1]),"+f"(c[2]),"+f"(c[3])
        : "r"(a[0]),"r"(a[1]),"r"(a[2]),"r"(a[3]), "r"(b0),"r"(b1));
}

__device__ __forceinline__ void cpasync16(u32 dst, const void* src){
    asm volatile("cp.async.cg.shared.global [%0], [%1], 16;" :: "r"(dst), "l"(src));
}

// ---------------- setup ----------------
__global__ void k_setup(const float* __restrict__ Wih, const float* __restrict__ Whh,
                        const float* __restrict__ bih, const float* __restrict__ bhh,
                        const float* __restrict__ Wdh, const float* __restrict__ Wc,
                        const float* __restrict__ Wh, const float* __restrict__ Wf){
    int tid0 = blockIdx.x*blockDim.x + threadIdx.x;
    int stride = gridDim.x*blockDim.x;
    for (int idx = tid0; idx < NG_*KG_; idx += stride){
        int n = idx / KG_;
        int k = idx - n*KG_;
        int j = n >> 2, g = n & 3;
        int no = g*512 + j;
        float v = (k < 256) ? Wih[no*256 + k] : Whh[no*H_ + (k-256)];
        g_Wg16[idx] = __float2half(v);
    }
    for (int idx = tid0; idx < H_*F_; idx += stride){
        float v = Wdh[idx];
        __half h = __float2half(v);
        g_Wdh16[idx] = h;
        g_WdhR[idx]  = __float2half((v - __half2float(h))*1024.f);
    }
    for (int idx = tid0; idx < F_*2*F_; idx += stride){
        float v = Wc[idx];
        __half h = __float2half(v);
        g_Wc16[idx] = h;
        g_WcR[idx]  = __float2half((v - __half2float(h))*1024.f);
    }
    for (int idx = tid0; idx < F_*H_; idx += stride)
        g_Wh16[idx] = __float2half(Wh[idx]);
    for (int idx = tid0; idx < F_*F_; idx += stride)
        g_Wf16[idx] = __float2half(Wf[idx]);
    for (int idx = tid0; idx < B_*H_; idx += stride){
        g_c[idx] = 0.f;
        g_h[idx] = 0.f;
        g_A16[(idx >> 9)*KG_ + 256 + (idx & 511)] = __float2half(0.f);
    }
    if (tid0 < NG_){
        int j = tid0 >> 2, g = tid0 & 3;
        int no = g*512 + j;
        g_bgR[tid0] = bih[no] + bhh[no];
    }
}

// ---------------- delta scan + gamma_x + alpha-input (fused) ----------------
__global__ void k_delta2(const int* __restrict__ mask, const float* __restrict__ Wdx,
                         const float* __restrict__ bdx){
    int idx = blockIdx.x*blockDim.x + threadIdx.x;
    int b = idx >> 7, f = idx & 127;
    const float wdx = Wdx[f*F_ + f];
    const float bx  = bdx[f];
    const int base = b*T_*F_ + f;
    float d = 0.f;
    for (int t = 0; t < T_; t++){
        int o = t*B_ + b;
        g_d16[o*F_ + f] = __float2half(d);
        float gx = expf(-fmaxf(d*wdx + bx, 0.f));
        float mp = (float)mask[base + t*F_];
        g_A216[o*256 + f]       = __float2half(gx);
        g_A216[o*256 + 128 + f] = __float2half(mp);
        d = mp + (1.f - mp)*(d + 1.f);
    }
}

// ---------------- 2-pass fp16 GEMM (precompute) ----------------
#define SSTR 72
#define R2P 320
#define B2P (R2P*SSTR)
#define SM2P (2*B2P*2)

template<int EPI>
__global__ void __launch_bounds__(256, 1)
gemm_2p(const __half* __restrict__ A, const __half* __restrict__ W,
        const __half* __restrict__ Wr, const float* __restrict__ bias,
        float* __restrict__ C, int N, int K)
{
    extern __shared__ __align__(16) __half smh[];
    const int tid = threadIdx.x, lane = tid & 31, wid = tid >> 5;
    const int m0 = blockIdx.y*64, n0 = blockIdx.x*128;
    const int wm = (wid & 1)*32, wn = (wid >> 1)*32;
    const int NC = K >> 6;

    float acc1[2][4][4], acc2[2][4][4];
    #pragma unroll
    for (int i=0;i<2;i++)
        #pragma unroll
        for (int j=0;j<4;j++)
            #pragma unroll
            for (int q=0;q<4;q++){ acc1[i][j][q]=0.f; acc2[i][j][q]=0.f; }

    const int aRow = lane & 15;
    const int aCol = ((lane >> 4) & 1) * 8;
    const int bRow = (lane & 7) + ((lane >> 4) & 1) * 8;
    const int bCol = ((lane >> 3) & 1) * 8;

    const __half* s_src[10]; int s_row[10];
    #pragma unroll
    for (int j = 0; j < 10; j++){
        int u = tid + j*256; int r = u >> 3;
        if (r < 64)      { s_src[j] = A;  s_row[j] = m0 + r; }
        else if (r < 192){ s_src[j] = W;  s_row[j] = n0 + r - 64; }
        else             { s_src[j] = Wr; s_row[j] = n0 + r - 192; }
    }

    {
        #pragma unroll
        for (int j = 0; j < 10; j++){
            int u = tid + j*256; int r = u >> 3, c = (u & 7)*8;
            cpasync16(sptr(&smh[r*SSTR + c]), &s_src[j][(size_t)s_row[j]*K + c]);
        }
        asm volatile("cp.async.commit_group;" ::: "memory");
    }

    for (int ch = 0; ch < NC; ch++){
        if (ch + 1 < NC){
            __half* tb = smh + ((ch+1)&1)*B2P;
            const int k1 = (ch+1)*64;
            #pragma unroll
            for (int j = 0; j < 10; j++){
                int u = tid + j*256; int r = u >> 3, c = (u & 7)*8;
                cpasync16(sptr(&tb[r*SSTR + c]), &s_src[j][(size_t)s_row[j]*K + k1 + c]);
            }
            asm volatile("cp.async.commit_group;" ::: "memory");
            asm volatile("cp.async.wait_group 1;" ::: "memory");
        } else {
            asm volatile("cp.async.wait_group 0;" ::: "memory");
        }
        __syncthreads();

        const __half* bb = smh + (ch&1)*B2P;
        const __half* As = bb;
        const __half* Ws = bb + 64*SSTR;
        const __half* Rs = bb + 192*SSTR;

        #pragma unroll
        for (int kk = 0; kk < 64; kk += 16){
            u32 a[2][4], bw[2][4], br[2][4];
            #pragma unroll
            for (int mt = 0; mt < 2; mt++)
                ldsm4(a[mt], sptr(&As[(wm + mt*16 + aRow)*SSTR + kk + aCol]));
            #pragma unroll
            for (int nt = 0; nt < 2; nt++){
                ldsm4(bw[nt], sptr(&Ws[(wn + nt*16 + bRow)*SSTR + kk + bCol]));
                ldsm4(br[nt], sptr(&Rs[(wn + nt*16 + bRow)*SSTR + kk + bCol]));
            }
            #pragma unroll
            for (int mt = 0; mt < 2; mt++)
                #pragma unroll
                for (int nj = 0; nj < 4; nj++){
                    const u32* pw = &bw[nj >> 1][(nj & 1) * 2];
                    const u32* pr = &br[nj >> 1][(nj & 1) * 2];
                    mma16816h(acc1[mt][nj], a[mt], pw[0], pw[1]);
                    mma16816h(acc2[mt][nj], a[mt], pr[0], pr[1]);
                }
        }
        __syncthreads();
    }

    const float rs = 1.f/1024.f;
    #pragma unroll
    for (int mt = 0; mt < 2; mt++){
        int row = m0 + wm + mt*16 + (lane >> 2);
        #pragma unroll
        for (int nj = 0; nj < 4; nj++){
            int col = n0 + wn + nj*8 + (lane & 3)*2;
            float b0v = bias[col], b1v = bias[col+1];
            float v[4] = { acc1[mt][nj][0] + acc2[mt][nj][0]*rs + b0v,
                           acc1[mt][nj][1] + acc2[mt][nj][1]*rs + b1v,
                           acc1[mt][nj][2] + acc2[mt][nj][2]*rs + b0v,
                           acc1[mt][nj][3] + acc2[mt][nj][3]*rs + b1v };
            #pragma unroll
            for (int q = 0; q < 4; q++){
                if (EPI == 1)      v[q] = expf(-fmaxf(v[q], 0.f));
                else if (EPI == 2) v[q] = 1.f/(1.f+expf(-v[q]));
            }
            C[(size_t)row*N + col]         = v[0];
            C[(size_t)row*N + col + 1]     = v[1];
            C[(size_t)(row+8)*N + col]     = v[2];
            C[(size_t)(row+8)*N + col + 1] = v[3];
        }
    }
}

// ---------------- gates GEMM (K=768) + fused LSTM epilogue ----------------
// 64(M) x 64(N) tiles, 128 threads (2x2 warps of 32x32), grid (32, 8) = 256 CTAs.
// Smaller tiles -> ~half regs/CTA -> 2+ CTAs/SM for latency hiding.
#define RGC 128                    // 64 A + 64 W rows per buffer
#define BGC (RGC*SSTR)             // halfs per buffer
#define SMGC (2*BGC*2)             // 36864 bytes

__global__ void __launch_bounds__(128, 2)
gemm_g(int t)
{
    extern __shared__ __align__(16) __half smh[];
    const __half* A = g_A16;
    const __half* W = g_Wg16;
    const int tid = threadIdx.x, lane = tid & 31, wid = tid >> 5;
    const int m0 = blockIdx.y*64, n0 = blockIdx.x*64;
    const int wm = (wid & 1)*32, wn = (wid >> 1)*32;
    const int NC = KG_ >> 6;   // 12

    float acc[2][4][4];
    #pragma unroll
    for (int i=0;i<2;i++)
        #pragma unroll
        for (int j=0;j<4;j++)
            #pragma unroll
            for (int q=0;q<4;q++) acc[i][j][q] = 0.f;

    const int aRow = lane & 15;
    const int aCol = ((lane >> 4) & 1) * 8;
    const int bRow = (lane & 7) + ((lane >> 4) & 1) * 8;
    const int bCol = ((lane >> 3) & 1) * 8;

    const __half* s_src[8]; int s_row[8];
    #pragma unroll
    for (int j = 0; j < 8; j++){
        int u = tid + j*128; int r = u >> 3;
        if (r < 64){ s_src[j] = A; s_row[j] = m0 + r; }
        else       { s_src[j] = W; s_row[j] = n0 + r - 64; }
    }

    {
        #pragma unroll
        for (int j = 0; j < 8; j++){
            int u = tid + j*128; int r = u >> 3, c = (u & 7)*8;
            cpasync16(sptr(&smh[r*SSTR + c]), &s_src[j][(size_t)s_row[j]*KG_ + c]);
        }
        asm volatile("cp.async.commit_group;" ::: "memory");
    }

    for (int ch = 0; ch < NC; ch++){
        if (ch + 1 < NC){
            __half* tb = smh + ((ch+1)&1)*BGC;
            const int k1 = (ch+1)*64;
            #pragma unroll
            for (int j = 0; j < 8; j++){
                int u = tid + j*128; int r = u >> 3, c = (u & 7)*8;
                cpasync16(sptr(&tb[r*SSTR + c]), &s_src[j][(size_t)s_row[j]*KG_ + k1 + c]);
            }
            asm volatile("cp.async.commit_group;" ::: "memory");
            asm volatile("cp.async.wait_group 1;" ::: "memory");
        } else {
            asm volatile("cp.async.wait_group 0;" ::: "memory");
        }
        __syncthreads();

        const __half* bb = smh + (ch&1)*BGC;
        const __half* As = bb;
        const __half* Ws = bb + 64*SSTR;

        #pragma unroll
        for (int kk = 0; kk < 64; kk += 16){
            u32 a[2][4], b[2][4];
            #pragma unroll
            for (int mt = 0; mt < 2; mt++)
                ldsm4(a[mt], sptr(&As[(wm + mt*16 + aRow)*SSTR + kk + aCol]));
            #pragma unroll
            for (int nt = 0; nt < 2; nt++)
                ldsm4(b[nt], sptr(&Ws[(wn + nt*16 + bRow)*SSTR + kk + bCol]));
            #pragma unroll
            for (int mt = 0; mt < 2; mt++)
                #pragma unroll
                for (int nj = 0; nj < 4; nj++){
                    const u32* pb = &b[nj >> 1][(nj & 1) * 2];
                    mma16816h(acc[mt][nj], a[mt], pb[0], pb[1]);
                }
        }
        __syncthreads();
    }

    // ---- epilogue: gates = acc + bias -> LSTM cell update ----
    float* Cs = (float*)smh;   // 64x64 fp32 = 16KB overlay
    #pragma unroll
    for (int mt = 0; mt < 2; mt++){
        int rl = wm + mt*16 + (lane >> 2);
        #pragma unroll
        for (int nj = 0; nj < 4; nj++){
            int cl = wn + nj*8 + (lane & 3)*2;
            float b0v = g_bgR[n0 + cl], b1v = g_bgR[n0 + cl + 1];
            Cs[rl*64 + cl]         = acc[mt][nj][0] + b0v;
            Cs[rl*64 + cl + 1]     = acc[mt][nj][1] + b1v;
            Cs[(rl+8)*64 + cl]     = acc[mt][nj][2] + b0v;
            Cs[(rl+8)*64 + cl + 1] = acc[mt][nj][3] + b1v;
        }
    }
    __syncthreads();

    const int u0 = n0 >> 2;   // 16 hidden units per CTA
    #pragma unroll
    for (int i = 0; i < 8; i++){
        int cidx = tid + i*128;
        int bl = cidx >> 4, jl = cidx & 15;
        float4 gv = *(const float4*)&Cs[bl*64 + jl*4];   // i, f, g, o
        float ig = sigmoidf_(gv.x);
        float fg = sigmoidf_(gv.y);
        float gg = tanhf(gv.z);
        float og = sigmoidf_(gv.w);
        int gb = m0 + bl;
        int ju = u0 + jl;
        float c = fg * g_c[gb*H_ + ju] + ig*gg;
        g_c[gb*H_ + ju] = c;
        float h = og * tanhf(c);
        g_h[gb*H_ + ju] = h;
        float hd = h * g_gammah[(size_t)((t+1)*B_ + gb)*H_ + ju];
        g_A16[gb*KG_ + 256 + ju] = __float2half(hd);
    }
}

// ---------------- per-step kernel: x_h, z_h, outputs, A[c_c|m] ----------------
// 128 CTAs x 256 threads, 4 batches/CTA. Weights staged as fp16 (half L2 traffic).
__global__ void __launch_bounds__(256)
k_step2(int t, const float* __restrict__ x, const int* __restrict__ mask,
        const float* __restrict__ bh, const float* __restrict__ bf,
        float* __restrict__ out)
{
    __shared__ float hs[4][512];
    __shared__ __half Wt[32][132];
    __shared__ float xh_s[4][128];
    __shared__ float xc_s[4][128];
    __shared__ float wfdiag[128];
    const int tid = threadIdx.x;
    const int b0  = blockIdx.x << 2;

    if (tid < 128) wfdiag[tid] = __half2float(g_Wf16[tid*F_ + tid]);

    for (int idx = tid; idx < 4*512; idx += 256)
        hs[idx >> 9][idx & 511] = g_h[(b0 + (idx >> 9))*H_ + (idx & 511)];
    __syncthreads();

    const int n  = tid & 127;
    const int hb = tid >> 7;

    // ---- x_h = h @ Wh^T + bh ----
    float acc[2] = {0.f, 0.f};
    for (int k0 = 0; k0 < H_; k0 += 32){
        for (int idx = tid; idx < 128*32; idx += 256){
            int nn = idx >> 5, kk = idx & 31;
            Wt[kk][nn] = g_Wh16[nn*H_ + k0 + kk];
        }
        __syncthreads();
        #pragma unroll
        for (int k4 = 0; k4 < 8; k4++){
            float4 hv0 = *(const float4*)&hs[hb*2+0][k0 + k4*4];
            float4 hv1 = *(const float4*)&hs[hb*2+1][k0 + k4*4];
            #pragma unroll
            for (int c2 = 0; c2 < 4; c2++){
                float w = __half2float(Wt[k4*4 + c2][n]);
                acc[0] += w * ((&hv0.x)[c2]);
                acc[1] += w * ((&hv1.x)[c2]);
            }
        }
        __syncthreads();
    }

    float m_r[2], x_r[2];
    {
        float bhv = bh[n];
        #pragma unroll
        for (int i = 0; i < 2; i++){
            int b = hb*2 + i, gb = b0 + b;
            float xh = acc[i] + bhv;
            xh_s[b][n] = xh;
            int gi = gb*T_*F_ + t*F_ + n;
            float mv = (float)mask[gi];
            float xv = x[gi];
            m_r[i] = mv; x_r[i] = xv;
            xc_s[b][n] = mv*xv + (1.f - mv)*xh;
            out[3*BTF_ + gi] = xh;
        }
    }
    __syncthreads();

    // ---- z_h = x_c @ Wf^T (off-diag) + bf ----
    float acc2[2] = {0.f, 0.f};
    for (int k0 = 0; k0 < F_; k0 += 32){
        for (int idx = tid; idx < 128*32; idx += 256){
            int nn = idx >> 5, kk = idx & 31;
            Wt[kk][nn] = g_Wf16[nn*F_ + k0 + kk];
        }
        __syncthreads();
        #pragma unroll
        for (int k4 = 0; k4 < 8; k4++){
            float4 v0 = *(const float4*)&xc_s[hb*2+0][k0 + k4*4];
            float4 v1 = *(const float4*)&xc_s[hb*2+1][k0 + k4*4];
            #pragma unroll
            for (int c2 = 0; c2 < 4; c2++){
                float w = __half2float(Wt[k4*4 + c2][n]);
                acc2[0] += w * ((&v0.x)[c2]);
                acc2[1] += w * ((&v1.x)[c2]);
            }
        }
        __syncthreads();
    }

    {
        float bfv = bf[n];
        float wfd = wfdiag[n];
        #pragma unroll
        for (int i = 0; i < 2; i++){
            int b = hb*2 + i, gb = b0 + b;
            float xc = xc_s[b][n];
            float z  = acc2[i] + bfv - xc*wfd;   // cancels fp16 diagonal exactly
            float al = g_alpha[(size_t)(t*B_ + gb)*F_ + n];
            float xh = xh_s[b][n];
            float ch = al*z + (1.f - al)*xh;
            float cc = m_r[i]*x_r[i] + (1.f - m_r[i])*ch;
            int gi = gb*T_*F_ + t*F_ + n;
            out[gi]          = cc;
            out[BTF_  + gi]  = ch;
            out[2*BTF_+ gi]  = z;
            g_A16[gb*KG_ + n]       = __float2half(cc);
            g_A16[gb*KG_ + 128 + n] = __float2half(m_r[i]);
        }
    }
}

// ---------------- launch ----------------
extern "C" void kernel_launch(void* const* d_in, const int* in_sizes, int n_in,
                              void* d_out, int out_size)
{
    const float* x    = (const float*)d_in[0];
    const int*   mask = (const int*  )d_in[1];
    const float* Wdh  = (const float*)d_in[2];
    const float* bdh  = (const float*)d_in[3];
    const float* Wdx  = (const float*)d_in[4];
    const float* bdx  = (const float*)d_in[5];
    const float* Wh   = (const float*)d_in[6];
    const float* bh   = (const float*)d_in[7];
    const float* Wf   = (const float*)d_in[8];
    const float* bf   = (const float*)d_in[9];
    const float* Wc   = (const float*)d_in[10];
    const float* bc   = (const float*)d_in[11];
    const float* Wih  = (const float*)d_in[12];
    const float* Whh  = (const float*)d_in[13];
    const float* bih  = (const float*)d_in[14];
    const float* bhh  = (const float*)d_in[15];
    float* out = (float*)d_out;

    void *pD16, *pA216, *pWdh16, *pWdhR, *pWc16, *pWcR, *pGammah, *pAlpha;
    cudaGetSymbolAddress(&pD16,    g_d16);
    cudaGetSymbolAddress(&pA216,   g_A216);
    cudaGetSymbolAddress(&pWdh16,  g_Wdh16);
    cudaGetSymbolAddress(&pWdhR,   g_WdhR);
    cudaGetSymbolAddress(&pWc16,   g_Wc16);
    cudaGetSymbolAddress(&pWcR,    g_WcR);
    cudaGetSymbolAddress(&pGammah, g_gammah);
    cudaGetSymbolAddress(&pAlpha,  g_alpha);

    cudaFuncSetAttribute(gemm_2p<1>, cudaFuncAttributeMaxDynamicSharedMemorySize, SM2P);
    cudaFuncSetAttribute(gemm_2p<2>, cudaFuncAttributeMaxDynamicSharedMemorySize, SM2P);
    cudaFuncSetAttribute(gemm_g,     cudaFuncAttributeMaxDynamicSharedMemorySize, SMGC);

    // setup + time-parallel precomputes
    k_setup<<<2048, 256>>>(Wih, Whh, bih, bhh, Wdh, Wc, Wh, Wf);
    k_delta2<<<256, 256>>>(mask, Wdx, bdx);
    gemm_2p<1><<<dim3(H_/128, TB_/64), 256, SM2P>>>(
        (const __half*)pD16, (const __half*)pWdh16, (const __half*)pWdhR,
        bdh, (float*)pGammah, H_, F_);
    gemm_2p<2><<<dim3(F_/128, TB_/64), 256, SM2P>>>(
        (const __half*)pA216, (const __half*)pWc16, (const __half*)pWcR,
        bc, (float*)pAlpha, F_, 2*F_);

    // sequential recurrence: 96 steps
    for (int t = 0; t < T_; t++){
        k_step2<<<128, 256>>>(t, x, mask, bh, bf, out);
        if (t < T_ - 1){
            // gates = A16 @ Wg16^T + bg -> LSTM update (h, c, A16 hγ slice)
            gemm_g<<<dim3(NG_/64, B_/64), 128, SMGC>>>(t);
        }
    }
}

// round 14
// speedup vs baseline: 2.5383x; 1.6331x over previous
#include <cuda_runtime.h>
#include <cuda_fp16.h>
#include <cstdint>
#include <math.h>

#define B_ 512
#define T_ 96
#define F_ 128
#define H_ 512
#define TB_ (T_*B_)        // 49152
#define BTF_ (B_*T_*F_)    // 6291456
#define KG_ 768            // gates GEMM K = 2F + H
#define NG_ 2048           // 4H
#define NCTA 128

typedef unsigned int u32;

// ---------------- scratch (device globals: no allocation allowed) ----------------
__device__ __align__(16) __half g_d16[TB_*F_];     // delta (integer, fp16 exact)
__device__ float g_gammah[TB_*H_];                 // [t*B+b, h]
__device__ __align__(16) __half g_A216[TB_*2*F_];  // [t*B+b, gx|m]
__device__ float g_alpha[TB_*F_];
__device__ __align__(16) __half g_A16[B_*KG_];     // per-step A = [c_c | m | h*gamma]
__device__ float g_c[B_*H_];
__device__ float g_h[B_*H_];
__device__ __align__(16) __half g_Wg16[NG_*KG_];   // [Wih|Whh] fused, gate-interleaved
__device__ float g_bgR[NG_];                       // bih+bhh, gate-interleaved
__device__ __align__(16) __half g_Wdh16[H_*F_];
__device__ __align__(16) __half g_WdhR[H_*F_];     // (W - fp16(W))*1024
__device__ __align__(16) __half g_Wc16[F_*2*F_];
__device__ __align__(16) __half g_WcR[F_*2*F_];
__device__ __align__(16) __half2 g_Wh2[256*128];   // Wh packed [k2][n]
__device__ __align__(16) __half2 g_Wf2[64*128];    // Wf packed [k2][n]
__device__ float g_wfdiag[128];
// grid barrier state (zero-initialized)
__device__ unsigned g_barcnt;
__device__ volatile unsigned g_bargen;

__device__ __forceinline__ float sigmoidf_(float v){ return 1.f/(1.f+expf(-v)); }

__device__ __forceinline__ u32 sptr(const void* p){
    return (u32)__cvta_generic_to_shared(p);
}

__device__ __forceinline__ void ldsm4(u32* r, u32 addr){
    asm volatile("ldmatrix.sync.aligned.m8n8.x4.shared.b16 {%0,%1,%2,%3}, [%4];"
        : "=r"(r[0]),"=r"(r[1]),"=r"(r[2]),"=r"(r[3]) : "r"(addr));
}

__device__ __forceinline__ void mma16816h(float* c, const u32* a, u32 b0, u32 b1){
    asm volatile("mma.sync.aligned.m16n8k16.row.col.f32.f16.f16.f32 "
        "{%0,%1,%2,%3},{%4,%5,%6,%7},{%8,%9},{%0,%1,%2,%3};"
        : "+f"(c[0]),"+f"(c[1]),"+f"(c[2]),"+f"(c[3])
        : "r"(a[0]),"r"(a[1]),"r"(a[2]),"r"(a[3]), "r"(b0),"r"(b1));
}

__device__ __forceinline__ void cpasync16(u32 dst, const void* src){
    asm volatile("cp.async.cg.shared.global [%0], [%1], 16;" :: "r"(dst), "l"(src));
}

// grid-wide barrier: all NCTA CTAs resident (1 CTA/SM). Release+acquire fences.
__device__ __forceinline__ void gridsync(){
    __syncthreads();
    __threadfence();                        // release: make writes visible
    if (threadIdx.x == 0){
        unsigned gen = g_bargen;
        if (atomicAdd(&g_barcnt, 1u) == NCTA-1u){
            g_barcnt = 0;
            __threadfence();
            g_bargen = gen + 1u;
        } else {
            while (g_bargen == gen) { }
        }
    }
    __syncthreads();
    __threadfence();                        // acquire: invalidate stale L1
}

// ---------------- setup ----------------
__global__ void k_setup(const float* __restrict__ Wih, const float* __restrict__ Whh,
                        const float* __restrict__ bih, const float* __restrict__ bhh,
                        const float* __restrict__ Wdh, const float* __restrict__ Wc,
                        const float* __restrict__ Wh, const float* __restrict__ Wf){
    int tid0 = blockIdx.x*blockDim.x + threadIdx.x;
    int stride = gridDim.x*blockDim.x;
    for (int idx = tid0; idx < NG_*KG_; idx += stride){
        int n = idx / KG_;
        int k = idx - n*KG_;
        int j = n >> 2, g = n & 3;
        int no = g*512 + j;
        float v = (k < 256) ? Wih[no*256 + k] : Whh[no*H_ + (k-256)];
        g_Wg16[idx] = __float2half(v);
    }
    for (int idx = tid0; idx < H_*F_; idx += stride){
        float v = Wdh[idx];
        __half h = __float2half(v);
        g_Wdh16[idx] = h;
        g_WdhR[idx]  = __float2half((v - __half2float(h))*1024.f);
    }
    for (int idx = tid0; idx < F_*2*F_; idx += stride){
        float v = Wc[idx];
        __half h = __float2half(v);
        g_Wc16[idx] = h;
        g_WcR[idx]  = __float2half((v - __half2float(h))*1024.f);
    }
    for (int idx = tid0; idx < 256*128; idx += stride){
        int k2 = idx >> 7, n = idx & 127;
        g_Wh2[idx] = __floats2half2_rn(Wh[n*H_ + 2*k2], Wh[n*H_ + 2*k2 + 1]);
    }
    for (int idx = tid0; idx < 64*128; idx += stride){
        int k2 = idx >> 7, n = idx & 127;
        g_Wf2[idx] = __floats2half2_rn(Wf[n*F_ + 2*k2], Wf[n*F_ + 2*k2 + 1]);
    }
    for (int idx = tid0; idx < B_*H_; idx += stride){
        g_c[idx] = 0.f;
        g_h[idx] = 0.f;
        g_A16[(idx >> 9)*KG_ + 256 + (idx & 511)] = __float2half(0.f);
    }
    if (tid0 < NG_){
        int j = tid0 >> 2, g = tid0 & 3;
        int no = g*512 + j;
        g_bgR[tid0] = bih[no] + bhh[no];
    }
    if (tid0 < 128)
        g_wfdiag[tid0] = __half2float(__float2half(Wf[tid0*F_ + tid0]));
}

// ---------------- delta scan + gamma_x + alpha-input (fused) ----------------
__global__ void k_delta2(const int* __restrict__ mask, const float* __restrict__ Wdx,
                         const float* __restrict__ bdx){
    int idx = blockIdx.x*blockDim.x + threadIdx.x;
    int b = idx >> 7, f = idx & 127;
    const float wdx = Wdx[f*F_ + f];
    const float bx  = bdx[f];
    const int base = b*T_*F_ + f;
    float d = 0.f;
    for (int t = 0; t < T_; t++){
        int o = t*B_ + b;
        g_d16[o*F_ + f] = __float2half(d);
        float gx = expf(-fmaxf(d*wdx + bx, 0.f));
        float mp = (float)mask[base + t*F_];
        g_A216[o*256 + f]       = __float2half(gx);
        g_A216[o*256 + 128 + f] = __float2half(mp);
        d = mp + (1.f - mp)*(d + 1.f);
    }
}

// ---------------- 2-pass fp16 GEMM (precompute) ----------------
#define SSTR 72
#define R2P 320
#define B2P (R2P*SSTR)
#define SM2P (2*B2P*2)

template<int EPI>
__global__ void __launch_bounds__(256, 1)
gemm_2p(const __half* __restrict__ A, const __half* __restrict__ W,
        const __half* __restrict__ Wr, const float* __restrict__ bias,
        float* __restrict__ C, int N, int K)
{
    extern __shared__ __align__(16) __half smh[];
    const int tid = threadIdx.x, lane = tid & 31, wid = tid >> 5;
    const int m0 = blockIdx.y*64, n0 = blockIdx.x*128;
    const int wm = (wid & 1)*32, wn = (wid >> 1)*32;
    const int NC = K >> 6;

    float acc1[2][4][4], acc2[2][4][4];
    #pragma unroll
    for (int i=0;i<2;i++)
        #pragma unroll
        for (int j=0;j<4;j++)
            #pragma unroll
            for (int q=0;q<4;q++){ acc1[i][j][q]=0.f; acc2[i][j][q]=0.f; }

    const int aRow = lane & 15;
    const int aCol = ((lane >> 4) & 1) * 8;
    const int bRow = (lane & 7) + ((lane >> 4) & 1) * 8;
    const int bCol = ((lane >> 3) & 1) * 8;

    const __half* s_src[10]; int s_row[10];
    #pragma unroll
    for (int j = 0; j < 10; j++){
        int u = tid + j*256; int r = u >> 3;
        if (r < 64)      { s_src[j] = A;  s_row[j] = m0 + r; }
        else if (r < 192){ s_src[j] = W;  s_row[j] = n0 + r - 64; }
        else             { s_src[j] = Wr; s_row[j] = n0 + r - 192; }
    }

    {
        #pragma unroll
        for (int j = 0; j < 10; j++){
            int u = tid + j*256; int r = u >> 3, c = (u & 7)*8;
            cpasync16(sptr(&smh[r*SSTR + c]), &s_src[j][(size_t)s_row[j]*K + c]);
        }
        asm volatile("cp.async.commit_group;" ::: "memory");
    }

    for (int ch = 0; ch < NC; ch++){
        if (ch + 1 < NC){
            __half* tb = smh + ((ch+1)&1)*B2P;
            const int k1 = (ch+1)*64;
            #pragma unroll
            for (int j = 0; j < 10; j++){
                int u = tid + j*256; int r = u >> 3, c = (u & 7)*8;
                cpasync16(sptr(&tb[r*SSTR + c]), &s_src[j][(size_t)s_row[j]*K + k1 + c]);
            }
            asm volatile("cp.async.commit_group;" ::: "memory");
            asm volatile("cp.async.wait_group 1;" ::: "memory");
        } else {
            asm volatile("cp.async.wait_group 0;" ::: "memory");
        }
        __syncthreads();

        const __half* bb = smh + (ch&1)*B2P;
        const __half* As = bb;
        const __half* Ws = bb + 64*SSTR;
        const __half* Rs = bb + 192*SSTR;

        #pragma unroll
        for (int kk = 0; kk < 64; kk += 16){
            u32 a[2][4], bw[2][4], br[2][4];
            #pragma unroll
            for (int mt = 0; mt < 2; mt++)
                ldsm4(a[mt], sptr(&As[(wm + mt*16 + aRow)*SSTR + kk + aCol]));
            #pragma unroll
            for (int nt = 0; nt < 2; nt++){
                ldsm4(bw[nt], sptr(&Ws[(wn + nt*16 + bRow)*SSTR + kk + bCol]));
                ldsm4(br[nt], sptr(&Rs[(wn + nt*16 + bRow)*SSTR + kk + bCol]));
            }
            #pragma unroll
            for (int mt = 0; mt < 2; mt++)
                #pragma unroll
                for (int nj = 0; nj < 4; nj++){
                    const u32* pw = &bw[nj >> 1][(nj & 1) * 2];
                    const u32* pr = &br[nj >> 1][(nj & 1) * 2];
                    mma16816h(acc1[mt][nj], a[mt], pw[0], pw[1]);
                    mma16816h(acc2[mt][nj], a[mt], pr[0], pr[1]);
                }
        }
        __syncthreads();
    }

    const float rs = 1.f/1024.f;
    #pragma unroll
    for (int mt = 0; mt < 2; mt++){
        int row = m0 + wm + mt*16 + (lane >> 2);
        #pragma unroll
        for (int nj = 0; nj < 4; nj++){
            int col = n0 + wn + nj*8 + (lane & 3)*2;
            float b0v = bias[col], b1v = bias[col+1];
            float v[4] = { acc1[mt][nj][0] + acc2[mt][nj][0]*rs + b0v,
                           acc1[mt][nj][1] + acc2[mt][nj][1]*rs + b1v,
                           acc1[mt][nj][2] + acc2[mt][nj][2]*rs + b0v,
                           acc1[mt][nj][3] + acc2[mt][nj][3]*rs + b1v };
            #pragma unroll
            for (int q = 0; q < 4; q++){
                if (EPI == 1)      v[q] = expf(-fmaxf(v[q], 0.f));
                else if (EPI == 2) v[q] = 1.f/(1.f+expf(-v[q]));
            }
            C[(size_t)row*N + col]         = v[0];
            C[(size_t)row*N + col + 1]     = v[1];
            C[(size_t)(row+8)*N + col]     = v[2];
            C[(size_t)(row+8)*N + col + 1] = v[3];
        }
    }
}

// ---------------- persistent recurrence kernel ----------------
// smem layout: [wh2 131072B][wf2 32768B][wfdiag 512B][scratch 55296B]
#define WH_OFF  0
#define WF_OFF  131072
#define WFD_OFF 163840
#define SCR_OFF 164352
#define RG 192
#define BGH (RG*SSTR)              // halfs per gates buffer: 13824
#define SMR (SCR_OFF + 2*BGH*2)    // 219648 bytes total

__global__ void __launch_bounds__(256, 1)
k_recur(const float* __restrict__ x, const int* __restrict__ mask,
        const float* __restrict__ bh, const float* __restrict__ bf,
        float* __restrict__ out)
{
    extern __shared__ __align__(16) char sm[];
    const int tid = threadIdx.x, lane = tid & 31, wid = tid >> 5;
    const int bid = blockIdx.x;

    __half2* wh2 = (__half2*)(sm + WH_OFF);          // [256][128]
    __half2* wf2 = (__half2*)(sm + WF_OFF);          // [64][128]
    float*   wfd = (float*)(sm + WFD_OFF);
    // phase A overlay on scratch
    float* hs   = (float*)(sm + SCR_OFF);            // [4][512]
    float* xh_s = hs + 4*512;                        // [4][128]
    float* xc_s = xh_s + 4*128;                      // [4][128]
    // phase B overlay
    __half* smh = (__half*)(sm + SCR_OFF);

    // one-time stage of persistent weights
    for (int idx = tid; idx < 256*128; idx += 256) wh2[idx] = g_Wh2[idx];
    for (int idx = tid; idx < 64*128;  idx += 256) wf2[idx] = g_Wf2[idx];
    if (tid < 128) wfd[tid] = g_wfdiag[tid];
    __syncthreads();

    // phase A mapping
    const int b0 = bid << 2;                  // 4 batches per CTA
    const int n  = tid & 127;
    const int hb = tid >> 7;
    // phase B mapping (64M x 128N tiles, 8x16 grid)
    const int m0 = (bid >> 4)*64;
    const int n0 = (bid & 15)*128;
    const int wm = (wid & 1)*32, wn = (wid >> 1)*32;
    const int aRow = lane & 15;
    const int aCol = ((lane >> 4) & 1) * 8;
    const int bRow = (lane & 7) + ((lane >> 4) & 1) * 8;
    const int bCol = ((lane >> 3) & 1) * 8;
    const __half* s_srcA[6]; int s_rowA[6];
    #pragma unroll
    for (int j = 0; j < 6; j++){
        int u = tid + j*256; int r = u >> 3;
        if (r < 64){ s_srcA[j] = g_A16;  s_rowA[j] = m0 + r; }
        else       { s_srcA[j] = g_Wg16; s_rowA[j] = n0 + r - 64; }
    }

    for (int t = 0; t < T_; t++){
        // ================= phase A: x_h, z_h, outputs, A16[c_c|m] =================
        for (int idx = tid; idx < 2048; idx += 256)
            hs[idx] = g_h[b0*H_ + idx];
        __syncthreads();

        const float* h0 = hs + (hb*2+0)*512;
        const float* h1 = hs + (hb*2+1)*512;
        float acc0 = 0.f, acc1 = 0.f;
        #pragma unroll 8
        for (int k2 = 0; k2 < 256; k2++){
            float2 w = __half22float2(wh2[k2*128 + n]);
            float2 a = *(const float2*)(h0 + 2*k2);
            float2 b = *(const float2*)(h1 + 2*k2);
            acc0 += w.x*a.x + w.y*a.y;
            acc1 += w.x*b.x + w.y*b.y;
        }

        float m_r[2], x_r[2];
        {
            float bhv = bh[n];
            float accs[2] = {acc0, acc1};
            #pragma unroll
            for (int i = 0; i < 2; i++){
                int b = hb*2 + i, gb = b0 + b;
                float xh = accs[i] + bhv;
                xh_s[b*128 + n] = xh;
                int gi = gb*T_*F_ + t*F_ + n;
                float mv = (float)mask[gi];
                float xv = x[gi];
                m_r[i] = mv; x_r[i] = xv;
                xc_s[b*128 + n] = mv*xv + (1.f - mv)*xh;
                out[3*BTF_ + gi] = xh;
            }
        }
        __syncthreads();

        const float* c0 = xc_s + (hb*2+0)*128;
        const float* c1 = xc_s + (hb*2+1)*128;
        float zac0 = 0.f, zac1 = 0.f;
        #pragma unroll 8
        for (int k2 = 0; k2 < 64; k2++){
            float2 w = __half22float2(wf2[k2*128 + n]);
            float2 a = *(const float2*)(c0 + 2*k2);
            float2 b = *(const float2*)(c1 + 2*k2);
            zac0 += w.x*a.x + w.y*a.y;
            zac1 += w.x*b.x + w.y*b.y;
        }

        {
            float bfv = bf[n];
            float wfdv = wfd[n];
            float zacs[2] = {zac0, zac1};
            #pragma unroll
            for (int i = 0; i < 2; i++){
                int b = hb*2 + i, gb = b0 + b;
                float xc = xc_s[b*128 + n];
                float z  = zacs[i] + bfv - xc*wfdv;
                float al = g_alpha[(size_t)(t*B_ + gb)*F_ + n];
                float xh = xh_s[b*128 + n];
                float ch = al*z + (1.f - al)*xh;
                float cc = m_r[i]*x_r[i] + (1.f - m_r[i])*ch;
                int gi = gb*T_*F_ + t*F_ + n;
                out[gi]          = cc;
                out[BTF_  + gi]  = ch;
                out[2*BTF_+ gi]  = z;
                g_A16[gb*KG_ + n]       = __float2half(cc);
                g_A16[gb*KG_ + 128 + n] = __float2half(m_r[i]);
            }
        }

        gridsync();
        if (t == T_ - 1) break;

        // ================= phase B: gates GEMM + LSTM update =================
        float acc[2][4][4];
        #pragma unroll
        for (int i=0;i<2;i++)
            #pragma unroll
            for (int j=0;j<4;j++)
                #pragma unroll
                for (int q=0;q<4;q++) acc[i][j][q] = 0.f;

        {
            #pragma unroll
            for (int j = 0; j < 6; j++){
                int u = tid + j*256; int r = u >> 3, c = (u & 7)*8;
                cpasync16(sptr(&smh[r*SSTR + c]), &s_srcA[j][(size_t)s_rowA[j]*KG_ + c]);
            }
            asm volatile("cp.async.commit_group;" ::: "memory");
        }

        for (int ch = 0; ch < 12; ch++){
            if (ch + 1 < 12){
                __half* tb = smh + ((ch+1)&1)*BGH;
                const int k1 = (ch+1)*64;
                #pragma unroll
                for (int j = 0; j < 6; j++){
                    int u = tid + j*256; int r = u >> 3, c = (u & 7)*8;
                    cpasync16(sptr(&tb[r*SSTR + c]), &s_srcA[j][(size_t)s_rowA[j]*KG_ + k1 + c]);
                }
                asm volatile("cp.async.commit_group;" ::: "memory");
                asm volatile("cp.async.wait_group 1;" ::: "memory");
            } else {
                asm volatile("cp.async.wait_group 0;" ::: "memory");
            }
            __syncthreads();

            const __half* bb = smh + (ch&1)*BGH;
            const __half* As = bb;
            const __half* Ws = bb + 64*SSTR;

            #pragma unroll
            for (int kk = 0; kk < 64; kk += 16){
                u32 a[2][4], b[2][4];
                #pragma unroll
                for (int mt = 0; mt < 2; mt++)
                    ldsm4(a[mt], sptr(&As[(wm + mt*16 + aRow)*SSTR + kk + aCol]));
                #pragma unroll
                for (int nt = 0; nt < 2; nt++)
                    ldsm4(b[nt], sptr(&Ws[(wn + nt*16 + bRow)*SSTR + kk + bCol]));
                #pragma unroll
                for (int mt = 0; mt < 2; mt++)
                    #pragma unroll
                    for (int nj = 0; nj < 4; nj++){
                        const u32* pb = &b[nj >> 1][(nj & 1) * 2];
                        mma16816h(acc[mt][nj], a[mt], pb[0], pb[1]);
                    }
            }
            __syncthreads();
        }

        // epilogue: gates = acc + bias -> LSTM update
        float* Cs = (float*)smh;   // 64x128 fp32 = 32KB overlay
        #pragma unroll
        for (int mt = 0; mt < 2; mt++){
            int rl = wm + mt*16 + (lane >> 2);
            #pragma unroll
            for (int nj = 0; nj < 4; nj++){
                int cl = wn + nj*8 + (lane & 3)*2;
                float b0v = g_bgR[n0 + cl], b1v = g_bgR[n0 + cl + 1];
                Cs[rl*128 + cl]         = acc[mt][nj][0] + b0v;
                Cs[rl*128 + cl + 1]     = acc[mt][nj][1] + b1v;
                Cs[(rl+8)*128 + cl]     = acc[mt][nj][2] + b0v;
                Cs[(rl+8)*128 + cl + 1] = acc[mt][nj][3] + b1v;
            }
        }
        __syncthreads();

        const int u0 = n0 >> 2;   // 32 hidden units per CTA
        #pragma unroll
        for (int i = 0; i < 8; i++){
            int cidx = tid + i*256;
            int bl = cidx >> 5, jl = cidx & 31;
            float4 gv = *(const float4*)&Cs[bl*128 + jl*4];   // i, f, g, o
            float ig = sigmoidf_(gv.x);
            float fg = sigmoidf_(gv.y);
            float gg = tanhf(gv.z);
            float og = sigmoidf_(gv.w);
            int gb = m0 + bl;
            int ju = u0 + jl;
            float c = fg * g_c[gb*H_ + ju] + ig*gg;
            g_c[gb*H_ + ju] = c;
            float h = og * tanhf(c);
            g_h[gb*H_ + ju] = h;
            float hd = h * g_gammah[(size_t)((t+1)*B_ + gb)*H_ + ju];
            g_A16[gb*KG_ + 256 + ju] = __float2half(hd);
        }
        __syncthreads();   // protect Cs before next phase A overlays scratch

        gridsync();
    }
}

// ---------------- launch ----------------
extern "C" void kernel_launch(void* const* d_in, const int* in_sizes, int n_in,
                              void* d_out, int out_size)
{
    const float* x    = (const float*)d_in[0];
    const int*   mask = (const int*  )d_in[1];
    const float* Wdh  = (const float*)d_in[2];
    const float* bdh  = (const float*)d_in[3];
    const float* Wdx  = (const float*)d_in[4];
    const float* bdx  = (const float*)d_in[5];
    const float* Wh   = (const float*)d_in[6];
    const float* bh   = (const float*)d_in[7];
    const float* Wf   = (const float*)d_in[8];
    const float* bf   = (const float*)d_in[9];
    const float* Wc   = (const float*)d_in[10];
    const float* bc   = (const float*)d_in[11];
    const float* Wih  = (const float*)d_in[12];
    const float* Whh  = (const float*)d_in[13];
    const float* bih  = (const float*)d_in[14];
    const float* bhh  = (const float*)d_in[15];
    float* out = (float*)d_out;

    void *pD16, *pA216, *pWdh16, *pWdhR, *pWc16, *pWcR, *pGammah, *pAlpha;
    cudaGetSymbolAddress(&pD16,    g_d16);
    cudaGetSymbolAddress(&pA216,   g_A216);
    cudaGetSymbolAddress(&pWdh16,  g_Wdh16);
    cudaGetSymbolAddress(&pWdhR,   g_WdhR);
    cudaGetSymbolAddress(&pWc16,   g_Wc16);
    cudaGetSymbolAddress(&pWcR,    g_WcR);
    cudaGetSymbolAddress(&pGammah, g_gammah);
    cudaGetSymbolAddress(&pAlpha,  g_alpha);

    cudaFuncSetAttribute(gemm_2p<1>, cudaFuncAttributeMaxDynamicSharedMemorySize, SM2P);
    cudaFuncSetAttribute(gemm_2p<2>, cudaFuncAttributeMaxDynamicSharedMemorySize, SM2P);
    cudaFuncSetAttribute(k_recur,    cudaFuncAttributeMaxDynamicSharedMemorySize, SMR);

    // setup + time-parallel precomputes
    k_setup<<<2048, 256>>>(Wih, Whh, bih, bhh, Wdh, Wc, Wh, Wf);
    k_delta2<<<256, 256>>>(mask, Wdx, bdx);
    gemm_2p<1><<<dim3(H_/128, TB_/64), 256, SM2P>>>(
        (const __half*)pD16, (const __half*)pWdh16, (const __half*)pWdhR,
        bdh, (float*)pGammah, H_, F_);
    gemm_2p<2><<<dim3(F_/128, TB_/64), 256, SM2P>>>(
        (const __half*)pA216, (const __half*)pWc16, (const __half*)pWcR,
        bc, (float*)pAlpha, F_, 2*F_);

    // entire 96-step recurrence in ONE persistent kernel
    k_recur<<<NCTA, 256, SMR>>>(x, mask, bh, bf, out);
}